// round 11
// baseline (speedup 1.0000x reference)
#include <cuda_runtime.h>

#define NJ 24
#define TILE 2048          // points per block
#define PPT 8              // points per thread
#define CJ 2               // joints per chunk
#define NCHUNK 12          // 24 / 2
#define STAGES 3

// Ancestor chains (root -> joint) for the fixed SMPL tree.
__device__ const int d_chain[NJ][9] = {
    {0,0,0,0,0,0,0,0,0},
    {0,1,0,0,0,0,0,0,0},
    {0,2,0,0,0,0,0,0,0},
    {0,3,0,0,0,0,0,0,0},
    {0,1,4,0,0,0,0,0,0},
    {0,2,5,0,0,0,0,0,0},
    {0,3,6,0,0,0,0,0,0},
    {0,1,4,7,0,0,0,0,0},
    {0,2,5,8,0,0,0,0,0},
    {0,3,6,9,0,0,0,0,0},
    {0,1,4,7,10,0,0,0,0},
    {0,2,5,8,11,0,0,0,0},
    {0,3,6,9,12,0,0,0,0},
    {0,3,6,9,13,0,0,0,0},
    {0,3,6,9,14,0,0,0,0},
    {0,3,6,9,12,15,0,0,0},
    {0,3,6,9,13,16,0,0,0},
    {0,3,6,9,14,17,0,0,0},
    {0,3,6,9,13,16,18,0,0},
    {0,3,6,9,14,17,19,0,0},
    {0,3,6,9,13,16,18,20,0},
    {0,3,6,9,14,17,19,21,0},
    {0,3,6,9,13,16,18,20,22},
    {0,3,6,9,14,17,19,21,23},
};
__device__ const int d_chlen[NJ] = {1,2,2,2,3,3,3,4,4,4,5,5,5,5,5,6,6,6,7,7,8,8,9,9};

typedef unsigned long long u64;

__device__ __forceinline__ u64 fma2(u64 a, u64 b, u64 c) {
    u64 d;
    asm("fma.rn.f32x2 %0, %1, %2, %3;" : "=l"(d) : "l"(a), "l"(b), "l"(c));
    return d;
}
__device__ __forceinline__ u64 mul2(u64 a, u64 b) {
    u64 d;
    asm("mul.rn.f32x2 %0, %1, %2;" : "=l"(d) : "l"(a), "l"(b));
    return d;
}
__device__ __forceinline__ u64 pack_dup(float f) {
    unsigned int u = __float_as_uint(f);
    return ((u64)u << 32) | (u64)u;
}
__device__ __forceinline__ u64 pack2f(float lo, float hi) {
    u64 d;
    asm("mov.b64 %0, {%1, %2};" : "=l"(d) : "r"(__float_as_uint(lo)), "r"(__float_as_uint(hi)));
    return d;
}
__device__ __forceinline__ void unpack2f(u64 v, float& lo, float& hi) {
    unsigned int l, h;
    asm("mov.b64 {%0, %1}, %2;" : "=r"(l), "=r"(h) : "l"(v));
    lo = __uint_as_float(l);
    hi = __uint_as_float(h);
}
__device__ __forceinline__ void cp_async16(unsigned int dst_smem, const void* src) {
    asm volatile("cp.async.cg.shared.global [%0], [%1], 16;" :: "r"(dst_smem), "l"(src));
}
__device__ __forceinline__ void cp_commit() {
    asm volatile("cp.async.commit_group;");
}
template <int NLeft>
__device__ __forceinline__ void cp_wait() {
    asm volatile("cp.async.wait_group %0;" :: "n"(NLeft));
}

__global__ void skin_kernel(const float* __restrict__ normals,
                            const float* __restrict__ pose,
                            const float* __restrict__ W,
                            float* __restrict__ out,
                            int N)
{
    __shared__ float sLoc[NJ][9];                  // local per-joint rotations
    __shared__ u64   sRp[NJ][9];                   // composed rotations, f32x2-duplicated
    __shared__ __align__(16) float sW[STAGES][CJ][TILE];  // 48 KB weight ring

    const int b = blockIdx.y;
    const int tid = threadIdx.x;

    // --- Rodrigues (one thread per joint) ---
    if (tid < NJ) {
        const float x = pose[b * 72 + tid * 3 + 0];
        const float y = pose[b * 72 + tid * 3 + 1];
        const float z = pose[b * 72 + tid * 3 + 2];
        const float e = 1e-8f;
        const float a = sqrtf((x + e) * (x + e) + (y + e) * (y + e) + (z + e) * (z + e));
        const float inv = 1.0f / a;
        const float ux = x * inv, uy = y * inv, uz = z * inv;
        float s, c;
        sincosf(a, &s, &c);
        const float C = 1.0f - c;
        sLoc[tid][0] = c + C * ux * ux;
        sLoc[tid][1] = C * ux * uy - s * uz;
        sLoc[tid][2] = C * ux * uz + s * uy;
        sLoc[tid][3] = C * uy * ux + s * uz;
        sLoc[tid][4] = c + C * uy * uy;
        sLoc[tid][5] = C * uy * uz - s * ux;
        sLoc[tid][6] = C * uz * ux - s * uy;
        sLoc[tid][7] = C * uz * uy + s * ux;
        sLoc[tid][8] = c + C * uz * uz;
    }
    __syncthreads();

    // --- parallel chain composition ---
    if (tid < NJ) {
        float R[9];
        #pragma unroll
        for (int e2 = 0; e2 < 9; e2++) R[e2] = sLoc[0][e2];
        const int len = d_chlen[tid];
        for (int i = 1; i < len; i++) {
            const int j = d_chain[tid][i];
            float T[9];
            #pragma unroll
            for (int r = 0; r < 3; r++)
                #pragma unroll
                for (int cc = 0; cc < 3; cc++)
                    T[r * 3 + cc] = R[r * 3 + 0] * sLoc[j][0 * 3 + cc]
                                  + R[r * 3 + 1] * sLoc[j][1 * 3 + cc]
                                  + R[r * 3 + 2] * sLoc[j][2 * 3 + cc];
            #pragma unroll
            for (int e2 = 0; e2 < 9; e2++) R[e2] = T[e2];
        }
        #pragma unroll
        for (int e2 = 0; e2 < 9; e2++) sRp[tid][e2] = pack_dup(R[e2]);
    }
    __syncthreads();

    const float* Nb = normals + (size_t)b * 3 * N;
    const float* Wb = W + (size_t)b * NJ * N;
    float* Ob = out + (size_t)b * 3 * N;

    const int tile_n = blockIdx.x * TILE;
    const int n = tile_n + tid * PPT;              // this thread's first point
    const bool full = (n + PPT <= N);

    const unsigned int sw_base =
        (unsigned int)__cvta_generic_to_shared(&sW[0][0][0]) + (unsigned int)tid * (PPT * 4u);
    const float* wsrc0 = Wb + n;                   // + joint*N

    // ---- pipeline prologue: issue chunks 0 and 1 ----
    #pragma unroll
    for (int c = 0; c < STAGES - 1; c++) {
        if (full) {
            const unsigned int dst = sw_base + (unsigned int)(c % STAGES) * (CJ * TILE * 4);
            #pragma unroll
            for (int j = 0; j < CJ; j++) {
                const float* src = wsrc0 + (size_t)(c * CJ + j) * N;
                cp_async16(dst + j * (TILE * 4), src);
                cp_async16(dst + j * (TILE * 4) + 16, src + 4);
            }
        }
        cp_commit();
    }

    if (full) {
        // load + pack 8 normals per axis (4 f32x2 pairs per axis)
        u64 nx[4], ny[4], nz[4];
        {
            const float4 x0 = __ldcs(reinterpret_cast<const float4*>(Nb + n));
            const float4 x1 = __ldcs(reinterpret_cast<const float4*>(Nb + n + 4));
            nx[0] = pack2f(x0.x, x0.y); nx[1] = pack2f(x0.z, x0.w);
            nx[2] = pack2f(x1.x, x1.y); nx[3] = pack2f(x1.z, x1.w);
            const float4 y0 = __ldcs(reinterpret_cast<const float4*>(Nb + (size_t)N + n));
            const float4 y1 = __ldcs(reinterpret_cast<const float4*>(Nb + (size_t)N + n + 4));
            ny[0] = pack2f(y0.x, y0.y); ny[1] = pack2f(y0.z, y0.w);
            ny[2] = pack2f(y1.x, y1.y); ny[3] = pack2f(y1.z, y1.w);
            const float4 z0 = __ldcs(reinterpret_cast<const float4*>(Nb + 2 * (size_t)N + n));
            const float4 z1 = __ldcs(reinterpret_cast<const float4*>(Nb + 2 * (size_t)N + n + 4));
            nz[0] = pack2f(z0.x, z0.y); nz[1] = pack2f(z0.z, z0.w);
            nz[2] = pack2f(z1.x, z1.y); nz[3] = pack2f(z1.z, z1.w);
        }

        u64 acc0[4] = {0, 0, 0, 0};
        u64 acc1[4] = {0, 0, 0, 0};
        u64 acc2[4] = {0, 0, 0, 0};

        #pragma unroll
        for (int c = 0; c < NCHUNK; c++) {
            // issue chunk c+2 (if any), keep ring full
            if (c + STAGES - 1 < NCHUNK) {
                const unsigned int dst =
                    sw_base + (unsigned int)((c + STAGES - 1) % STAGES) * (CJ * TILE * 4);
                #pragma unroll
                for (int j = 0; j < CJ; j++) {
                    const float* src = wsrc0 + (size_t)((c + STAGES - 1) * CJ + j) * N;
                    cp_async16(dst + j * (TILE * 4), src);
                    cp_async16(dst + j * (TILE * 4) + 16, src + 4);
                }
            }
            cp_commit();
            cp_wait<STAGES - 1>();   // chunk c's group complete

            const int st = c % STAGES;
            #pragma unroll
            for (int j = 0; j < CJ; j++) {
                const int k = c * CJ + j;
                const float4 wv0 = *reinterpret_cast<const float4*>(&sW[st][j][tid * PPT]);
                const float4 wv1 = *reinterpret_cast<const float4*>(&sW[st][j][tid * PPT + 4]);
                u64 w[4];
                w[0] = pack2f(wv0.x, wv0.y); w[1] = pack2f(wv0.z, wv0.w);
                w[2] = pack2f(wv1.x, wv1.y); w[3] = pack2f(wv1.z, wv1.w);

                const u64 r0 = sRp[k][0], r1 = sRp[k][1], r2 = sRp[k][2];
                const u64 r3 = sRp[k][3], r4 = sRp[k][4], r5 = sRp[k][5];
                const u64 r6 = sRp[k][6], r7 = sRp[k][7], r8 = sRp[k][8];

                #pragma unroll
                for (int p = 0; p < 4; p++) {
                    u64 v;
                    v = mul2(r0, nx[p]); v = fma2(r1, ny[p], v); v = fma2(r2, nz[p], v);
                    acc0[p] = fma2(w[p], v, acc0[p]);
                    v = mul2(r3, nx[p]); v = fma2(r4, ny[p], v); v = fma2(r5, nz[p], v);
                    acc1[p] = fma2(w[p], v, acc1[p]);
                    v = mul2(r6, nx[p]); v = fma2(r7, ny[p], v); v = fma2(r8, nz[p], v);
                    acc2[p] = fma2(w[p], v, acc2[p]);
                }
            }
        }

        float4 o;
        unpack2f(acc0[0], o.x, o.y); unpack2f(acc0[1], o.z, o.w);
        __stcs(reinterpret_cast<float4*>(Ob + n), o);
        unpack2f(acc0[2], o.x, o.y); unpack2f(acc0[3], o.z, o.w);
        __stcs(reinterpret_cast<float4*>(Ob + n + 4), o);

        unpack2f(acc1[0], o.x, o.y); unpack2f(acc1[1], o.z, o.w);
        __stcs(reinterpret_cast<float4*>(Ob + (size_t)N + n), o);
        unpack2f(acc1[2], o.x, o.y); unpack2f(acc1[3], o.z, o.w);
        __stcs(reinterpret_cast<float4*>(Ob + (size_t)N + n + 4), o);

        unpack2f(acc2[0], o.x, o.y); unpack2f(acc2[1], o.z, o.w);
        __stcs(reinterpret_cast<float4*>(Ob + 2 * (size_t)N + n), o);
        unpack2f(acc2[2], o.x, o.y); unpack2f(acc2[3], o.z, o.w);
        __stcs(reinterpret_cast<float4*>(Ob + 2 * (size_t)N + n + 4), o);
    } else {
        // keep per-thread cp.async group bookkeeping consistent, then drain
        #pragma unroll
        for (int c = 0; c < NCHUNK; c++) cp_commit();
        cp_wait<0>();

        // scalar tail: points n .. min(n+PPT, N)
        for (int p = n; p < N && p < n + PPT; p++) {
            const float xs = Nb[p], ys = Nb[(size_t)N + p], zs = Nb[2 * (size_t)N + p];
            float o0 = 0.f, o1 = 0.f, o2 = 0.f;
            for (int k = 0; k < NJ; k++) {
                const float wv = Wb[(size_t)k * N + p];
                float r[9], hi;
                #pragma unroll
                for (int e2 = 0; e2 < 9; e2++) unpack2f(sRp[k][e2], r[e2], hi);
                o0 = fmaf(wv, r[0] * xs + r[1] * ys + r[2] * zs, o0);
                o1 = fmaf(wv, r[3] * xs + r[4] * ys + r[5] * zs, o1);
                o2 = fmaf(wv, r[6] * xs + r[7] * ys + r[8] * zs, o2);
            }
            Ob[p] = o0;
            Ob[(size_t)N + p] = o1;
            Ob[2 * (size_t)N + p] = o2;
        }
    }
}

extern "C" void kernel_launch(void* const* d_in, const int* in_sizes, int n_in,
                              void* d_out, int out_size)
{
    const float* normals = (const float*)d_in[0];   // (B,3,N)
    const float* pose    = (const float*)d_in[1];   // (B,72)
    const float* weights = (const float*)d_in[2];   // (B,24,N)
    float* out = (float*)d_out;                     // (B,3,N)

    const int B = in_sizes[1] / 72;
    const int N = in_sizes[0] / (3 * B);

    int gx = (N + TILE - 1) / TILE;
    if (gx < 1) gx = 1;

    dim3 block(256);
    dim3 grid(gx, B);
    skin_kernel<<<grid, block>>>(normals, pose, weights, out, N);
}

// round 12
// speedup vs baseline: 1.1429x; 1.1429x over previous
#include <cuda_runtime.h>

#define NJ 24
#define TILE 1024          // points per block
#define PPT 4              // points per thread
#define CJ 4               // joints per chunk
#define NCHUNK 6           // 24 / 4
#define STAGES 3

// Ancestor chains (root -> joint) for the fixed SMPL tree.
__device__ const int d_chain[NJ][9] = {
    {0,0,0,0,0,0,0,0,0},
    {0,1,0,0,0,0,0,0,0},
    {0,2,0,0,0,0,0,0,0},
    {0,3,0,0,0,0,0,0,0},
    {0,1,4,0,0,0,0,0,0},
    {0,2,5,0,0,0,0,0,0},
    {0,3,6,0,0,0,0,0,0},
    {0,1,4,7,0,0,0,0,0},
    {0,2,5,8,0,0,0,0,0},
    {0,3,6,9,0,0,0,0,0},
    {0,1,4,7,10,0,0,0,0},
    {0,2,5,8,11,0,0,0,0},
    {0,3,6,9,12,0,0,0,0},
    {0,3,6,9,13,0,0,0,0},
    {0,3,6,9,14,0,0,0,0},
    {0,3,6,9,12,15,0,0,0},
    {0,3,6,9,13,16,0,0,0},
    {0,3,6,9,14,17,0,0,0},
    {0,3,6,9,13,16,18,0,0},
    {0,3,6,9,14,17,19,0,0},
    {0,3,6,9,13,16,18,20,0},
    {0,3,6,9,14,17,19,21,0},
    {0,3,6,9,13,16,18,20,22},
    {0,3,6,9,14,17,19,21,23},
};
__device__ const int d_chlen[NJ] = {1,2,2,2,3,3,3,4,4,4,5,5,5,5,5,6,6,6,7,7,8,8,9,9};

typedef unsigned long long u64;

__device__ __forceinline__ u64 fma2(u64 a, u64 b, u64 c) {
    u64 d;
    asm("fma.rn.f32x2 %0, %1, %2, %3;" : "=l"(d) : "l"(a), "l"(b), "l"(c));
    return d;
}
__device__ __forceinline__ u64 mul2(u64 a, u64 b) {
    u64 d;
    asm("mul.rn.f32x2 %0, %1, %2;" : "=l"(d) : "l"(a), "l"(b));
    return d;
}
__device__ __forceinline__ u64 pack_dup(float f) {
    unsigned int u = __float_as_uint(f);
    return ((u64)u << 32) | (u64)u;
}
__device__ __forceinline__ u64 pack2f(float lo, float hi) {
    u64 d;
    asm("mov.b64 %0, {%1, %2};" : "=l"(d) : "r"(__float_as_uint(lo)), "r"(__float_as_uint(hi)));
    return d;
}
__device__ __forceinline__ void unpack2f(u64 v, float& lo, float& hi) {
    unsigned int l, h;
    asm("mov.b64 {%0, %1}, %2;" : "=r"(l), "=r"(h) : "l"(v));
    lo = __uint_as_float(l);
    hi = __uint_as_float(h);
}
__device__ __forceinline__ void cp_async16(unsigned int dst_smem, const void* src) {
    asm volatile("cp.async.cg.shared.global [%0], [%1], 16;" :: "r"(dst_smem), "l"(src));
}
__device__ __forceinline__ void cp_commit() {
    asm volatile("cp.async.commit_group;");
}
template <int NLeft>
__device__ __forceinline__ void cp_wait() {
    asm volatile("cp.async.wait_group %0;" :: "n"(NLeft));
}

__global__ void skin_kernel(const float* __restrict__ normals,
                            const float* __restrict__ pose,
                            const float* __restrict__ W,
                            float* __restrict__ out,
                            int N)
{
    __shared__ float sLoc[NJ][9];                  // local per-joint rotations
    __shared__ u64   sRp[NJ][9];                   // composed rotations, f32x2-duplicated
    __shared__ __align__(16) float sW[STAGES][CJ][TILE];  // 48 KB weight ring

    const int b = blockIdx.y;
    const int tid = threadIdx.x;

    const float* Nb = normals + (size_t)b * 3 * N;
    const float* Wb = W + (size_t)b * NJ * N;
    float* Ob = out + (size_t)b * 3 * N;

    const int tile_n = blockIdx.x * TILE;
    const int n = tile_n + tid * PPT;              // this thread's first point
    const bool full = (n + PPT <= N);

    const unsigned int sw_base =
        (unsigned int)__cvta_generic_to_shared(&sW[0][0][0]) + (unsigned int)tid * 16u;
    const float* wsrc0 = Wb + n;                   // + joint*N

    // ---- issue pipeline-fill chunks 0 and 1 FIRST: their DRAM flight time
    //      hides the entire Rodrigues + chain-compose prologue below ----
    #pragma unroll
    for (int c = 0; c < STAGES - 1; c++) {
        if (full) {
            const unsigned int dst = sw_base + (unsigned int)(c % STAGES) * (CJ * TILE * 4);
            #pragma unroll
            for (int j = 0; j < CJ; j++)
                cp_async16(dst + j * (TILE * 4), wsrc0 + (size_t)(c * CJ + j) * N);
        }
        cp_commit();
    }

    // --- Rodrigues (one thread per joint) ---
    if (tid < NJ) {
        const float x = pose[b * 72 + tid * 3 + 0];
        const float y = pose[b * 72 + tid * 3 + 1];
        const float z = pose[b * 72 + tid * 3 + 2];
        const float e = 1e-8f;
        const float a = sqrtf((x + e) * (x + e) + (y + e) * (y + e) + (z + e) * (z + e));
        const float inv = 1.0f / a;
        const float ux = x * inv, uy = y * inv, uz = z * inv;
        float s, c;
        sincosf(a, &s, &c);
        const float C = 1.0f - c;
        sLoc[tid][0] = c + C * ux * ux;
        sLoc[tid][1] = C * ux * uy - s * uz;
        sLoc[tid][2] = C * ux * uz + s * uy;
        sLoc[tid][3] = C * uy * ux + s * uz;
        sLoc[tid][4] = c + C * uy * uy;
        sLoc[tid][5] = C * uy * uz - s * ux;
        sLoc[tid][6] = C * uz * ux - s * uy;
        sLoc[tid][7] = C * uz * uy + s * ux;
        sLoc[tid][8] = c + C * uz * uz;
    }
    __syncthreads();

    // --- parallel chain composition ---
    if (tid < NJ) {
        float R[9];
        #pragma unroll
        for (int e2 = 0; e2 < 9; e2++) R[e2] = sLoc[0][e2];
        const int len = d_chlen[tid];
        for (int i = 1; i < len; i++) {
            const int j = d_chain[tid][i];
            float T[9];
            #pragma unroll
            for (int r = 0; r < 3; r++)
                #pragma unroll
                for (int cc = 0; cc < 3; cc++)
                    T[r * 3 + cc] = R[r * 3 + 0] * sLoc[j][0 * 3 + cc]
                                  + R[r * 3 + 1] * sLoc[j][1 * 3 + cc]
                                  + R[r * 3 + 2] * sLoc[j][2 * 3 + cc];
            #pragma unroll
            for (int e2 = 0; e2 < 9; e2++) R[e2] = T[e2];
        }
        #pragma unroll
        for (int e2 = 0; e2 < 9; e2++) sRp[tid][e2] = pack_dup(R[e2]);
    }
    __syncthreads();

    if (full) {
        // load + pack 4 normals per axis (latency overlaps chunk-0 wait)
        const float4 nxv = __ldcs(reinterpret_cast<const float4*>(Nb + n));
        const float4 nyv = __ldcs(reinterpret_cast<const float4*>(Nb + (size_t)N + n));
        const float4 nzv = __ldcs(reinterpret_cast<const float4*>(Nb + 2 * (size_t)N + n));
        const u64 nx0 = pack2f(nxv.x, nxv.y), nx1 = pack2f(nxv.z, nxv.w);
        const u64 ny0 = pack2f(nyv.x, nyv.y), ny1 = pack2f(nyv.z, nyv.w);
        const u64 nz0 = pack2f(nzv.x, nzv.y), nz1 = pack2f(nzv.z, nzv.w);

        u64 a00 = 0, a01 = 0, a10 = 0, a11 = 0, a20 = 0, a21 = 0;

        #pragma unroll
        for (int c = 0; c < NCHUNK; c++) {
            // issue chunk c+2 (if any), keep ring full
            if (c + STAGES - 1 < NCHUNK) {
                const unsigned int dst =
                    sw_base + (unsigned int)((c + STAGES - 1) % STAGES) * (CJ * TILE * 4);
                #pragma unroll
                for (int j = 0; j < CJ; j++)
                    cp_async16(dst + j * (TILE * 4),
                               wsrc0 + (size_t)((c + STAGES - 1) * CJ + j) * N);
            }
            cp_commit();
            cp_wait<STAGES - 1>();   // chunk c's group complete

            const int st = c % STAGES;
            #pragma unroll
            for (int j = 0; j < CJ; j++) {
                const int k = c * CJ + j;
                const float4 wv = *reinterpret_cast<const float4*>(&sW[st][j][tid * PPT]);
                const u64 w0 = pack2f(wv.x, wv.y);
                const u64 w1 = pack2f(wv.z, wv.w);

                const u64 r0 = sRp[k][0], r1 = sRp[k][1], r2 = sRp[k][2];
                const u64 r3 = sRp[k][3], r4 = sRp[k][4], r5 = sRp[k][5];
                const u64 r6 = sRp[k][6], r7 = sRp[k][7], r8 = sRp[k][8];

                u64 v;
                v = mul2(r0, nx0); v = fma2(r1, ny0, v); v = fma2(r2, nz0, v);
                a00 = fma2(w0, v, a00);
                v = mul2(r0, nx1); v = fma2(r1, ny1, v); v = fma2(r2, nz1, v);
                a01 = fma2(w1, v, a01);

                v = mul2(r3, nx0); v = fma2(r4, ny0, v); v = fma2(r5, nz0, v);
                a10 = fma2(w0, v, a10);
                v = mul2(r3, nx1); v = fma2(r4, ny1, v); v = fma2(r5, nz1, v);
                a11 = fma2(w1, v, a11);

                v = mul2(r6, nx0); v = fma2(r7, ny0, v); v = fma2(r8, nz0, v);
                a20 = fma2(w0, v, a20);
                v = mul2(r6, nx1); v = fma2(r7, ny1, v); v = fma2(r8, nz1, v);
                a21 = fma2(w1, v, a21);
            }
        }

        float4 o;
        unpack2f(a00, o.x, o.y); unpack2f(a01, o.z, o.w);
        __stcs(reinterpret_cast<float4*>(Ob + n), o);
        unpack2f(a10, o.x, o.y); unpack2f(a11, o.z, o.w);
        __stcs(reinterpret_cast<float4*>(Ob + (size_t)N + n), o);
        unpack2f(a20, o.x, o.y); unpack2f(a21, o.z, o.w);
        __stcs(reinterpret_cast<float4*>(Ob + 2 * (size_t)N + n), o);
    } else {
        // drain the empty/unused groups so pipeline state is consistent
        #pragma unroll
        for (int c = 0; c < NCHUNK; c++) cp_commit();
        cp_wait<0>();

        // scalar tail: points n .. min(n+4, N)
        for (int p = n; p < N && p < n + PPT; p++) {
            const float xs = Nb[p], ys = Nb[(size_t)N + p], zs = Nb[2 * (size_t)N + p];
            float o0 = 0.f, o1 = 0.f, o2 = 0.f;
            for (int k = 0; k < NJ; k++) {
                const float wv = Wb[(size_t)k * N + p];
                float r[9], hi;
                #pragma unroll
                for (int e2 = 0; e2 < 9; e2++) unpack2f(sRp[k][e2], r[e2], hi);
                o0 = fmaf(wv, r[0] * xs + r[1] * ys + r[2] * zs, o0);
                o1 = fmaf(wv, r[3] * xs + r[4] * ys + r[5] * zs, o1);
                o2 = fmaf(wv, r[6] * xs + r[7] * ys + r[8] * zs, o2);
            }
            Ob[p] = o0;
            Ob[(size_t)N + p] = o1;
            Ob[2 * (size_t)N + p] = o2;
        }
    }
}

extern "C" void kernel_launch(void* const* d_in, const int* in_sizes, int n_in,
                              void* d_out, int out_size)
{
    const float* normals = (const float*)d_in[0];   // (B,3,N)
    const float* pose    = (const float*)d_in[1];   // (B,72)
    const float* weights = (const float*)d_in[2];   // (B,24,N)
    float* out = (float*)d_out;                     // (B,3,N)

    const int B = in_sizes[1] / 72;
    const int N = in_sizes[0] / (3 * B);

    int gx = (N + TILE - 1) / TILE;
    if (gx < 1) gx = 1;

    dim3 block(256);
    dim3 grid(gx, B);
    skin_kernel<<<grid, block>>>(normals, pose, weights, out, N);
}

// round 13
// speedup vs baseline: 1.1596x; 1.0147x over previous
#include <cuda_runtime.h>

#define NJ 24
#define TILE 1024          // points per block
#define PPT 4              // points per thread
#define CJ 3               // joints per chunk
#define NCHUNK 8           // 24 / 3
#define STAGES 4

// Ancestor chains (root -> joint) for the fixed SMPL tree.
__device__ const int d_chain[NJ][9] = {
    {0,0,0,0,0,0,0,0,0},
    {0,1,0,0,0,0,0,0,0},
    {0,2,0,0,0,0,0,0,0},
    {0,3,0,0,0,0,0,0,0},
    {0,1,4,0,0,0,0,0,0},
    {0,2,5,0,0,0,0,0,0},
    {0,3,6,0,0,0,0,0,0},
    {0,1,4,7,0,0,0,0,0},
    {0,2,5,8,0,0,0,0,0},
    {0,3,6,9,0,0,0,0,0},
    {0,1,4,7,10,0,0,0,0},
    {0,2,5,8,11,0,0,0,0},
    {0,3,6,9,12,0,0,0,0},
    {0,3,6,9,13,0,0,0,0},
    {0,3,6,9,14,0,0,0,0},
    {0,3,6,9,12,15,0,0,0},
    {0,3,6,9,13,16,0,0,0},
    {0,3,6,9,14,17,0,0,0},
    {0,3,6,9,13,16,18,0,0},
    {0,3,6,9,14,17,19,0,0},
    {0,3,6,9,13,16,18,20,0},
    {0,3,6,9,14,17,19,21,0},
    {0,3,6,9,13,16,18,20,22},
    {0,3,6,9,14,17,19,21,23},
};
__device__ const int d_chlen[NJ] = {1,2,2,2,3,3,3,4,4,4,5,5,5,5,5,6,6,6,7,7,8,8,9,9};

typedef unsigned long long u64;

__device__ __forceinline__ u64 fma2(u64 a, u64 b, u64 c) {
    u64 d;
    asm("fma.rn.f32x2 %0, %1, %2, %3;" : "=l"(d) : "l"(a), "l"(b), "l"(c));
    return d;
}
__device__ __forceinline__ u64 mul2(u64 a, u64 b) {
    u64 d;
    asm("mul.rn.f32x2 %0, %1, %2;" : "=l"(d) : "l"(a), "l"(b));
    return d;
}
__device__ __forceinline__ u64 pack_dup(float f) {
    unsigned int u = __float_as_uint(f);
    return ((u64)u << 32) | (u64)u;
}
__device__ __forceinline__ u64 pack2f(float lo, float hi) {
    u64 d;
    asm("mov.b64 %0, {%1, %2};" : "=l"(d) : "r"(__float_as_uint(lo)), "r"(__float_as_uint(hi)));
    return d;
}
__device__ __forceinline__ void unpack2f(u64 v, float& lo, float& hi) {
    unsigned int l, h;
    asm("mov.b64 {%0, %1}, %2;" : "=r"(l), "=r"(h) : "l"(v));
    lo = __uint_as_float(l);
    hi = __uint_as_float(h);
}
__device__ __forceinline__ void cp_async16(unsigned int dst_smem, const void* src) {
    asm volatile("cp.async.cg.shared.global [%0], [%1], 16;" :: "r"(dst_smem), "l"(src));
}
__device__ __forceinline__ void cp_commit() {
    asm volatile("cp.async.commit_group;");
}
template <int NLeft>
__device__ __forceinline__ void cp_wait() {
    asm volatile("cp.async.wait_group %0;" :: "n"(NLeft));
}

__global__ void skin_kernel(const float* __restrict__ normals,
                            const float* __restrict__ pose,
                            const float* __restrict__ W,
                            float* __restrict__ out,
                            int N)
{
    __shared__ float sLoc[NJ][9];                      // local per-joint rotations
    __shared__ __align__(16) u64 sRp[NJ][12];          // composed rotations, f32x2-dup, padded rows
    __shared__ __align__(16) float sW[STAGES][CJ][TILE];  // 48 KB weight ring

    const int b = blockIdx.y;
    const int tid = threadIdx.x;

    const float* Nb = normals + (size_t)b * 3 * N;
    const float* Wb = W + (size_t)b * NJ * N;
    float* Ob = out + (size_t)b * 3 * N;

    const int tile_n = blockIdx.x * TILE;
    const int n = tile_n + tid * PPT;              // this thread's first point
    const bool full = (n + PPT <= N);

    const unsigned int sw_base =
        (unsigned int)__cvta_generic_to_shared(&sW[0][0][0]) + (unsigned int)tid * 16u;
    const float* wsrc0 = Wb + n;                   // + joint*N

    // ---- issue pipeline-fill chunks FIRST: their DRAM flight time hides the
    //      entire Rodrigues + chain-compose prologue below ----
    #pragma unroll
    for (int c = 0; c < STAGES - 1; c++) {
        if (full) {
            const unsigned int dst = sw_base + (unsigned int)(c % STAGES) * (CJ * TILE * 4);
            #pragma unroll
            for (int j = 0; j < CJ; j++)
                cp_async16(dst + j * (TILE * 4), wsrc0 + (size_t)(c * CJ + j) * N);
        }
        cp_commit();
    }

    // --- Rodrigues (one thread per joint) ---
    if (tid < NJ) {
        const float x = pose[b * 72 + tid * 3 + 0];
        const float y = pose[b * 72 + tid * 3 + 1];
        const float z = pose[b * 72 + tid * 3 + 2];
        const float e = 1e-8f;
        const float a = sqrtf((x + e) * (x + e) + (y + e) * (y + e) + (z + e) * (z + e));
        const float inv = 1.0f / a;
        const float ux = x * inv, uy = y * inv, uz = z * inv;
        float s, c;
        sincosf(a, &s, &c);
        const float C = 1.0f - c;
        sLoc[tid][0] = c + C * ux * ux;
        sLoc[tid][1] = C * ux * uy - s * uz;
        sLoc[tid][2] = C * ux * uz + s * uy;
        sLoc[tid][3] = C * uy * ux + s * uz;
        sLoc[tid][4] = c + C * uy * uy;
        sLoc[tid][5] = C * uy * uz - s * ux;
        sLoc[tid][6] = C * uz * ux - s * uy;
        sLoc[tid][7] = C * uz * uy + s * ux;
        sLoc[tid][8] = c + C * uz * uz;
    }
    __syncthreads();

    // --- parallel chain composition ---
    if (tid < NJ) {
        float R[9];
        #pragma unroll
        for (int e2 = 0; e2 < 9; e2++) R[e2] = sLoc[0][e2];
        const int len = d_chlen[tid];
        for (int i = 1; i < len; i++) {
            const int j = d_chain[tid][i];
            float T[9];
            #pragma unroll
            for (int r = 0; r < 3; r++)
                #pragma unroll
                for (int cc = 0; cc < 3; cc++)
                    T[r * 3 + cc] = R[r * 3 + 0] * sLoc[j][0 * 3 + cc]
                                  + R[r * 3 + 1] * sLoc[j][1 * 3 + cc]
                                  + R[r * 3 + 2] * sLoc[j][2 * 3 + cc];
            #pragma unroll
            for (int e2 = 0; e2 < 9; e2++) R[e2] = T[e2];
        }
        #pragma unroll
        for (int e2 = 0; e2 < 9; e2++) sRp[tid][e2] = pack_dup(R[e2]);
    }
    __syncthreads();

    if (full) {
        // load + pack 4 normals per axis (latency overlaps chunk-0 wait)
        const float4 nxv = __ldcs(reinterpret_cast<const float4*>(Nb + n));
        const float4 nyv = __ldcs(reinterpret_cast<const float4*>(Nb + (size_t)N + n));
        const float4 nzv = __ldcs(reinterpret_cast<const float4*>(Nb + 2 * (size_t)N + n));
        const u64 nx0 = pack2f(nxv.x, nxv.y), nx1 = pack2f(nxv.z, nxv.w);
        const u64 ny0 = pack2f(nyv.x, nyv.y), ny1 = pack2f(nyv.z, nyv.w);
        const u64 nz0 = pack2f(nzv.x, nzv.y), nz1 = pack2f(nzv.z, nzv.w);

        u64 a00 = 0, a01 = 0, a10 = 0, a11 = 0, a20 = 0, a21 = 0;

        #pragma unroll
        for (int c = 0; c < NCHUNK; c++) {
            // issue chunk c+STAGES-1 (if any), keep ring full
            if (c + STAGES - 1 < NCHUNK) {
                const unsigned int dst =
                    sw_base + (unsigned int)((c + STAGES - 1) % STAGES) * (CJ * TILE * 4);
                #pragma unroll
                for (int j = 0; j < CJ; j++)
                    cp_async16(dst + j * (TILE * 4),
                               wsrc0 + (size_t)((c + STAGES - 1) * CJ + j) * N);
            }
            cp_commit();
            cp_wait<STAGES - 1>();   // chunk c's group complete

            const int st = c % STAGES;
            #pragma unroll
            for (int j = 0; j < CJ; j++) {
                const int k = c * CJ + j;
                const float4 wv = *reinterpret_cast<const float4*>(&sW[st][j][tid * PPT]);
                const u64 w0 = pack2f(wv.x, wv.y);
                const u64 w1 = pack2f(wv.z, wv.w);

                // vectorized shared loads of R (LDS.128 x4 + LDS.64)
                const ulonglong2 r01 = *reinterpret_cast<const ulonglong2*>(&sRp[k][0]);
                const ulonglong2 r23 = *reinterpret_cast<const ulonglong2*>(&sRp[k][2]);
                const ulonglong2 r45 = *reinterpret_cast<const ulonglong2*>(&sRp[k][4]);
                const ulonglong2 r67 = *reinterpret_cast<const ulonglong2*>(&sRp[k][6]);
                const u64 r8 = sRp[k][8];

                u64 v;
                v = mul2(r01.x, nx0); v = fma2(r01.y, ny0, v); v = fma2(r23.x, nz0, v);
                a00 = fma2(w0, v, a00);
                v = mul2(r01.x, nx1); v = fma2(r01.y, ny1, v); v = fma2(r23.x, nz1, v);
                a01 = fma2(w1, v, a01);

                v = mul2(r23.y, nx0); v = fma2(r45.x, ny0, v); v = fma2(r45.y, nz0, v);
                a10 = fma2(w0, v, a10);
                v = mul2(r23.y, nx1); v = fma2(r45.x, ny1, v); v = fma2(r45.y, nz1, v);
                a11 = fma2(w1, v, a11);

                v = mul2(r67.x, nx0); v = fma2(r67.y, ny0, v); v = fma2(r8, nz0, v);
                a20 = fma2(w0, v, a20);
                v = mul2(r67.x, nx1); v = fma2(r67.y, ny1, v); v = fma2(r8, nz1, v);
                a21 = fma2(w1, v, a21);
            }
        }

        float4 o;
        unpack2f(a00, o.x, o.y); unpack2f(a01, o.z, o.w);
        __stcs(reinterpret_cast<float4*>(Ob + n), o);
        unpack2f(a10, o.x, o.y); unpack2f(a11, o.z, o.w);
        __stcs(reinterpret_cast<float4*>(Ob + (size_t)N + n), o);
        unpack2f(a20, o.x, o.y); unpack2f(a21, o.z, o.w);
        __stcs(reinterpret_cast<float4*>(Ob + 2 * (size_t)N + n), o);
    } else {
        // drain the empty/unused groups so pipeline state is consistent
        #pragma unroll
        for (int c = 0; c < NCHUNK; c++) cp_commit();
        cp_wait<0>();

        // scalar tail: points n .. min(n+4, N)
        for (int p = n; p < N && p < n + PPT; p++) {
            const float xs = Nb[p], ys = Nb[(size_t)N + p], zs = Nb[2 * (size_t)N + p];
            float o0 = 0.f, o1 = 0.f, o2 = 0.f;
            for (int k = 0; k < NJ; k++) {
                const float wv = Wb[(size_t)k * N + p];
                float r[9], hi;
                #pragma unroll
                for (int e2 = 0; e2 < 9; e2++) unpack2f(sRp[k][e2], r[e2], hi);
                o0 = fmaf(wv, r[0] * xs + r[1] * ys + r[2] * zs, o0);
                o1 = fmaf(wv, r[3] * xs + r[4] * ys + r[5] * zs, o1);
                o2 = fmaf(wv, r[6] * xs + r[7] * ys + r[8] * zs, o2);
            }
            Ob[p] = o0;
            Ob[(size_t)N + p] = o1;
            Ob[2 * (size_t)N + p] = o2;
        }
    }
}

extern "C" void kernel_launch(void* const* d_in, const int* in_sizes, int n_in,
                              void* d_out, int out_size)
{
    const float* normals = (const float*)d_in[0];   // (B,3,N)
    const float* pose    = (const float*)d_in[1];   // (B,72)
    const float* weights = (const float*)d_in[2];   // (B,24,N)
    float* out = (float*)d_out;                     // (B,3,N)

    const int B = in_sizes[1] / 72;
    const int N = in_sizes[0] / (3 * B);

    int gx = (N + TILE - 1) / TILE;
    if (gx < 1) gx = 1;

    dim3 block(256);
    dim3 grid(gx, B);
    skin_kernel<<<grid, block>>>(normals, pose, weights, out, N);
}